// round 8
// baseline (speedup 1.0000x reference)
#include <cuda_runtime.h>
#include <cuda_bf16.h>
#include <cstdint>

// ============================================================================
// out[n,o] = act_scale*wscale[o] * sum_k qa[n,k]*qw[o,k] + bias[o]
//   qa = clamp(rint(x/as), -128, 127)  (zp=128 cancels in (q-zp))
// Portable tensor-core path: cp.async + ldmatrix + mma.sync.m16n8k32.s8.
// R8: R7 winner + 4-phase ks stagger (per-SMSP + per-CTA offsets) and per-warp
//     nj rotation to flatten SM-wide crossbar bursts against tensor phases.
// ============================================================================

#define NROWS 4096
#define KDIM  4096
#define ODIM  4096

#define BM 128
#define BN 128
#define BK 128
#define STAGES 3
#define KTILES (KDIM / BK)                        // 32
#define STAGE_BYTES (BM * BK + BN * BK)           // 32768
#define GEMM_SMEM (STAGES * STAGE_BYTES + 1024)   // 99328 -> 2 CTAs/SM

__device__ __align__(128) int8_t g_Aq[(size_t)NROWS * KDIM];  // 16 MB
__device__ __align__(128) int8_t g_Bq[(size_t)ODIM * KDIM];   // 16 MB

// ---------------------------------------------------------------------------
__device__ __forceinline__ uint32_t smem_u32(const void* p) {
    uint32_t a;
    asm("{ .reg .u64 t; cvta.to.shared.u64 t, %1; cvt.u32.u64 %0, t; }"
        : "=r"(a) : "l"(p));
    return a;
}
__device__ __forceinline__ void cp_async16(uint32_t dst, const void* src) {
    asm volatile("cp.async.cg.shared.global [%0], [%1], 16;"
                 :: "r"(dst), "l"(src) : "memory");
}
__device__ __forceinline__ void cp_commit() {
    asm volatile("cp.async.commit_group;" ::: "memory");
}
template <int N>
__device__ __forceinline__ void cp_wait() {
    asm volatile("cp.async.wait_group %0;" :: "n"(N) : "memory");
}
__device__ __forceinline__ void ldmatrix_x4(uint32_t* r, uint32_t addr) {
    asm volatile("ldmatrix.sync.aligned.m8n8.x4.shared.b16 {%0,%1,%2,%3}, [%4];"
                 : "=r"(r[0]), "=r"(r[1]), "=r"(r[2]), "=r"(r[3]) : "r"(addr));
}
__device__ __forceinline__ void mma_s8(int* c, const uint32_t* a, const uint32_t* b) {
    asm volatile(
        "mma.sync.aligned.m16n8k32.row.col.s32.s8.s8.s32 "
        "{%0,%1,%2,%3}, {%4,%5,%6,%7}, {%8,%9}, {%0,%1,%2,%3};"
        : "+r"(c[0]), "+r"(c[1]), "+r"(c[2]), "+r"(c[3])
        : "r"(a[0]), "r"(a[1]), "r"(a[2]), "r"(a[3]), "r"(b[0]), "r"(b[1]));
}

// ---------------------------------------------------------------------------
// Fused quantize: fp32 -> int8 (q - zp), row-major scratch. 16 elems/thread.
// ---------------------------------------------------------------------------
#define QB 4096

__device__ __forceinline__ uint32_t quant_pack4(const float* v, float inv, float zp) {
    uint32_t w = 0;
#pragma unroll
    for (int i = 0; i < 4; ++i) {
        float t = rintf(v[i] * inv) + zp;
        t = fminf(fmaxf(t, 0.0f), 255.0f);
        int q = (int)t - (int)zp;
        w |= ((uint32_t)q & 0xFFu) << (i * 8);
    }
    return w;
}

__global__ void __launch_bounds__(256)
quant_fused_kernel(const float* __restrict__ x, const float* __restrict__ asp,
                   const int* __restrict__ azp,
                   const float* __restrict__ w, const float* __restrict__ wsc,
                   const int* __restrict__ wzp)
{
    bool is_w = blockIdx.x >= QB;
    int blk = is_w ? (blockIdx.x - QB) : blockIdx.x;
    size_t base = ((size_t)blk * 256 + threadIdx.x) * 16;
    const float* src = is_w ? w : x;
    int8_t* dst = is_w ? g_Bq : g_Aq;
    int row = (int)(base >> 12);
    float inv = is_w ? (1.0f / wsc[row]) : (1.0f / *asp);
    float zp  = is_w ? (float)wzp[row]   : (float)(*azp);
    float v[16];
    *reinterpret_cast<float4*>(v)      = *reinterpret_cast<const float4*>(src + base);
    *reinterpret_cast<float4*>(v + 4)  = *reinterpret_cast<const float4*>(src + base + 4);
    *reinterpret_cast<float4*>(v + 8)  = *reinterpret_cast<const float4*>(src + base + 8);
    *reinterpret_cast<float4*>(v + 12) = *reinterpret_cast<const float4*>(src + base + 12);
    uint4 o;
    o.x = quant_pack4(v,      inv, zp);
    o.y = quant_pack4(v + 4,  inv, zp);
    o.z = quant_pack4(v + 8,  inv, zp);
    o.w = quant_pack4(v + 12, inv, zp);
    *reinterpret_cast<uint4*>(dst + base) = o;
}

// ---------------------------------------------------------------------------
// GEMM: 128x128 per CTA, 8 warps (4x2), warp tile 32x64, IMMA m16n8k32.s8,
// 2 CTAs/SM. SMEM 16B-chunk XOR swizzle: chunk' = chunk ^ (row & 7).
// 4-phase ks stagger + per-warp nj rotation to flatten crossbar bursts.
// ---------------------------------------------------------------------------
__device__ __forceinline__ void load_stage(uint32_t stA, int m0, int n0, int kt, int tid)
{
    uint32_t stB = stA + BM * BK;
#pragma unroll
    for (int i = 0; i < 4; ++i) {
        int id = tid + i * 256;           // A: 128 rows x 8 chunks
        int row = id >> 3, ch = id & 7;
        cp_async16(stA + row * BK + (((uint32_t)(ch ^ (row & 7))) << 4),
                   g_Aq + (size_t)(m0 + row) * KDIM + kt * BK + ch * 16);
    }
#pragma unroll
    for (int i = 0; i < 4; ++i) {
        int id = tid + i * 256;           // B: 128 rows x 8 chunks
        int row = id >> 3, ch = id & 7;
        cp_async16(stB + row * BK + (((uint32_t)(ch ^ (row & 7))) << 4),
                   g_Bq + (size_t)(n0 + row) * KDIM + kt * BK + ch * 16);
    }
}

__global__ void __launch_bounds__(256, 2)
gemm_q_kernel(const float* __restrict__ bias, const float* __restrict__ act_scale_p,
              const float* __restrict__ wscale, float* __restrict__ out)
{
    extern __shared__ char smem[];
    const uint32_t sb = (smem_u32(smem) + 1023u) & ~1023u;
    const int tid = threadIdx.x;
    const int lane = tid & 31;
    const int wid = tid >> 5;
    const int wm = wid & 3;               // 0..3 (32-row slices)
    const int wn = wid >> 2;              // 0..1 (64-col slices)
    // 4-phase stagger: SMSP pair (w, w+4) differ by 2; adjacent SMSPs by 1;
    // the two co-resident CTAs offset by their tile-coordinate parity.
    const int phase = ((((wid >> 2) << 1) | (wid & 1))
                       + (int)((blockIdx.x + blockIdx.y) & 3)) & 3;
    const int njrot = wid & 3;
    const int m0 = blockIdx.y * BM;
    const int n0 = blockIdx.x * BN;

    int acc[2][8][4];
#pragma unroll
    for (int mi = 0; mi < 2; ++mi)
#pragma unroll
        for (int ni = 0; ni < 8; ++ni)
#pragma unroll
            for (int j = 0; j < 4; ++j) acc[mi][ni][j] = 0;

#pragma unroll
    for (int s = 0; s < STAGES - 1; ++s) {
        load_stage(sb + s * STAGE_BYTES, m0, n0, s, tid);
        cp_commit();
    }

    const int mat = lane >> 3;
    const int rsel = (lane & 7) + (mat & 1) * 8;
    const int csel = mat >> 1;

    for (int kt = 0; kt < KTILES; ++kt) {
        cp_wait<STAGES - 2>();
        __syncthreads();

        int nxt = kt + STAGES - 1;
        if (nxt < KTILES)
            load_stage(sb + (nxt % STAGES) * STAGE_BYTES, m0, n0, nxt, tid);
        cp_commit();

        const uint32_t aT = sb + (kt % STAGES) * STAGE_BYTES;
        const uint32_t bT = aT + BM * BK;

#pragma unroll
        for (int ksi = 0; ksi < 4; ++ksi) {
            const int ks = (ksi + phase) & 3;     // staggered across warps/CTAs
            const int ch = ks * 2 + csel;
            uint32_t aF[2][4];
#pragma unroll
            for (int mi = 0; mi < 2; ++mi) {
                int row = wm * 32 + mi * 16 + rsel;
                ldmatrix_x4(aF[mi], aT + row * BK + (((uint32_t)(ch ^ (row & 7))) << 4));
            }
            uint32_t bF[8][2];
#pragma unroll
            for (int nj = 0; nj < 4; ++nj) {
                int njr = (nj + njrot) & 3;       // rotate B burst order per warp
                int n = wn * 64 + njr * 16 + rsel;
                uint32_t r[4];
                ldmatrix_x4(r, bT + n * BK + (((uint32_t)(ch ^ (n & 7))) << 4));
                bF[njr * 2][0] = r[0]; bF[njr * 2 + 1][0] = r[1];
                bF[njr * 2][1] = r[2]; bF[njr * 2 + 1][1] = r[3];
            }
#pragma unroll
            for (int mi = 0; mi < 2; ++mi)
#pragma unroll
                for (int ni = 0; ni < 8; ++ni)
                    mma_s8(acc[mi][ni], aF[mi], bF[ni]);
        }
    }
    cp_wait<0>();

    // ---- epilogue: scale + bias, direct-to-global (no staging, no syncs) ----
    const float as = *act_scale_p;
    const int r4 = lane >> 2;             // 0..7
    const int c2 = (lane & 3) * 2;        // 0,2,4,6

#pragma unroll
    for (int ni = 0; ni < 8; ++ni) {
        int gc = n0 + wn * 64 + ni * 8 + c2;
        float sw0 = as * wscale[gc],     bv0 = bias[gc];
        float sw1 = as * wscale[gc + 1], bv1 = bias[gc + 1];
#pragma unroll
        for (int mi = 0; mi < 2; ++mi) {
            int r = m0 + wm * 32 + mi * 16 + r4;
            float2 v0, v1;
            v0.x = fmaf(__int2float_rn(acc[mi][ni][0]), sw0, bv0);
            v0.y = fmaf(__int2float_rn(acc[mi][ni][1]), sw1, bv1);
            v1.x = fmaf(__int2float_rn(acc[mi][ni][2]), sw0, bv0);
            v1.y = fmaf(__int2float_rn(acc[mi][ni][3]), sw1, bv1);
            *reinterpret_cast<float2*>(&out[(size_t)r * ODIM + gc])       = v0;
            *reinterpret_cast<float2*>(&out[(size_t)(r + 8) * ODIM + gc]) = v1;
        }
    }
}

// ---------------------------------------------------------------------------
extern "C" void kernel_launch(void* const* d_in, const int* in_sizes, int n_in,
                              void* d_out, int out_size) {
    (void)in_sizes; (void)n_in; (void)out_size;
    const float* x         = (const float*)d_in[0];
    const float* weight    = (const float*)d_in[1];
    const float* bias      = (const float*)d_in[2];
    const float* act_scale = (const float*)d_in[3];
    const int*   act_zp    = (const int*)d_in[4];
    const float* wscale    = (const float*)d_in[5];
    const int*   wzp       = (const int*)d_in[6];
    float* out = (float*)d_out;

    cudaFuncSetAttribute(gemm_q_kernel, cudaFuncAttributeMaxDynamicSharedMemorySize, GEMM_SMEM);

    quant_fused_kernel<<<2 * QB, 256>>>(x, act_scale, act_zp, weight, wscale, wzp);

    dim3 grid(ODIM / BN, NROWS / BM);   // (32, 32)
    gemm_q_kernel<<<grid, 256, GEMM_SMEM>>>(bias, act_scale, wscale, out);
}

// round 11
// speedup vs baseline: 1.8230x; 1.8230x over previous
#include <cuda_runtime.h>
#include <cuda_bf16.h>
#include <cstdint>

// ============================================================================
// out[n,o] = act_scale*wscale[o] * sum_k qa[n,k]*qw[o,k] + bias[o]
//   qa = clamp(rint(x/as), -128, 127)  (zp=128 cancels in (q-zp))
// Portable tensor-core path: cp.async + ldmatrix + mma.sync.m16n8k32.s8.
// R9 resubmit #2 (two prior rounds died to container infra; kernel never ran):
// R7 winner + 4-phase ks stagger (ADDRESS-ONLY; R8's nj register-array
// rotation caused local-memory spills and is removed).
// ============================================================================

#define NROWS 4096
#define KDIM  4096
#define ODIM  4096

#define BM 128
#define BN 128
#define BK 128
#define STAGES 3
#define KTILES (KDIM / BK)                        // 32
#define STAGE_BYTES (BM * BK + BN * BK)           // 32768
#define GEMM_SMEM (STAGES * STAGE_BYTES + 1024)   // 99328 -> 2 CTAs/SM

__device__ __align__(128) int8_t g_Aq[(size_t)NROWS * KDIM];  // 16 MB
__device__ __align__(128) int8_t g_Bq[(size_t)ODIM * KDIM];   // 16 MB

// ---------------------------------------------------------------------------
__device__ __forceinline__ uint32_t smem_u32(const void* p) {
    uint32_t a;
    asm("{ .reg .u64 t; cvta.to.shared.u64 t, %1; cvt.u32.u64 %0, t; }"
        : "=r"(a) : "l"(p));
    return a;
}
__device__ __forceinline__ void cp_async16(uint32_t dst, const void* src) {
    asm volatile("cp.async.cg.shared.global [%0], [%1], 16;"
                 :: "r"(dst), "l"(src) : "memory");
}
__device__ __forceinline__ void cp_commit() {
    asm volatile("cp.async.commit_group;" ::: "memory");
}
template <int N>
__device__ __forceinline__ void cp_wait() {
    asm volatile("cp.async.wait_group %0;" :: "n"(N) : "memory");
}
__device__ __forceinline__ void ldmatrix_x4(uint32_t* r, uint32_t addr) {
    asm volatile("ldmatrix.sync.aligned.m8n8.x4.shared.b16 {%0,%1,%2,%3}, [%4];"
                 : "=r"(r[0]), "=r"(r[1]), "=r"(r[2]), "=r"(r[3]) : "r"(addr));
}
__device__ __forceinline__ void mma_s8(int* c, const uint32_t* a, const uint32_t* b) {
    asm volatile(
        "mma.sync.aligned.m16n8k32.row.col.s32.s8.s8.s32 "
        "{%0,%1,%2,%3}, {%4,%5,%6,%7}, {%8,%9}, {%0,%1,%2,%3};"
        : "+r"(c[0]), "+r"(c[1]), "+r"(c[2]), "+r"(c[3])
        : "r"(a[0]), "r"(a[1]), "r"(a[2]), "r"(a[3]), "r"(b[0]), "r"(b[1]));
}

// ---------------------------------------------------------------------------
// Fused quantize: fp32 -> int8 (q - zp), row-major scratch. 16 elems/thread.
// ---------------------------------------------------------------------------
#define QB 4096

__device__ __forceinline__ uint32_t quant_pack4(const float* v, float inv, float zp) {
    uint32_t w = 0;
#pragma unroll
    for (int i = 0; i < 4; ++i) {
        float t = rintf(v[i] * inv) + zp;
        t = fminf(fmaxf(t, 0.0f), 255.0f);
        int q = (int)t - (int)zp;
        w |= ((uint32_t)q & 0xFFu) << (i * 8);
    }
    return w;
}

__global__ void __launch_bounds__(256)
quant_fused_kernel(const float* __restrict__ x, const float* __restrict__ asp,
                   const int* __restrict__ azp,
                   const float* __restrict__ w, const float* __restrict__ wsc,
                   const int* __restrict__ wzp)
{
    bool is_w = blockIdx.x >= QB;
    int blk = is_w ? (blockIdx.x - QB) : blockIdx.x;
    size_t base = ((size_t)blk * 256 + threadIdx.x) * 16;
    const float* src = is_w ? w : x;
    int8_t* dst = is_w ? g_Bq : g_Aq;
    int row = (int)(base >> 12);
    float inv = is_w ? (1.0f / wsc[row]) : (1.0f / *asp);
    float zp  = is_w ? (float)wzp[row]   : (float)(*azp);
    float v[16];
    *reinterpret_cast<float4*>(v)      = *reinterpret_cast<const float4*>(src + base);
    *reinterpret_cast<float4*>(v + 4)  = *reinterpret_cast<const float4*>(src + base + 4);
    *reinterpret_cast<float4*>(v + 8)  = *reinterpret_cast<const float4*>(src + base + 8);
    *reinterpret_cast<float4*>(v + 12) = *reinterpret_cast<const float4*>(src + base + 12);
    uint4 o;
    o.x = quant_pack4(v,      inv, zp);
    o.y = quant_pack4(v + 4,  inv, zp);
    o.z = quant_pack4(v + 8,  inv, zp);
    o.w = quant_pack4(v + 12, inv, zp);
    *reinterpret_cast<uint4*>(dst + base) = o;
}

// ---------------------------------------------------------------------------
// GEMM: 128x128 per CTA, 8 warps (4x2), warp tile 32x64, IMMA m16n8k32.s8,
// 2 CTAs/SM. SMEM 16B-chunk XOR swizzle: chunk' = chunk ^ (row & 7).
// 4-phase ks stagger (address-only): SMSP pairs differ by 2, adjacent SMSPs
// by 1, co-resident CTAs by tile parity. Register arrays keep constant
// subscripts (R8 lesson: runtime subscripts => local-memory spill).
// ---------------------------------------------------------------------------
__device__ __forceinline__ void load_stage(uint32_t stA, int m0, int n0, int kt, int tid)
{
    uint32_t stB = stA + BM * BK;
#pragma unroll
    for (int i = 0; i < 4; ++i) {
        int id = tid + i * 256;           // A: 128 rows x 8 chunks
        int row = id >> 3, ch = id & 7;
        cp_async16(stA + row * BK + (((uint32_t)(ch ^ (row & 7))) << 4),
                   g_Aq + (size_t)(m0 + row) * KDIM + kt * BK + ch * 16);
    }
#pragma unroll
    for (int i = 0; i < 4; ++i) {
        int id = tid + i * 256;           // B: 128 rows x 8 chunks
        int row = id >> 3, ch = id & 7;
        cp_async16(stB + row * BK + (((uint32_t)(ch ^ (row & 7))) << 4),
                   g_Bq + (size_t)(n0 + row) * KDIM + kt * BK + ch * 16);
    }
}

__global__ void __launch_bounds__(256, 2)
gemm_q_kernel(const float* __restrict__ bias, const float* __restrict__ act_scale_p,
              const float* __restrict__ wscale, float* __restrict__ out)
{
    extern __shared__ char smem[];
    const uint32_t sb = (smem_u32(smem) + 1023u) & ~1023u;
    const int tid = threadIdx.x;
    const int lane = tid & 31;
    const int wid = tid >> 5;
    const int wm = wid & 3;               // 0..3 (32-row slices)
    const int wn = wid >> 2;              // 0..1 (64-col slices)
    const int phase = ((((wid >> 2) << 1) | (wid & 1))
                       + (int)((blockIdx.x + blockIdx.y) & 3)) & 3;
    const int m0 = blockIdx.y * BM;
    const int n0 = blockIdx.x * BN;

    int acc[2][8][4];
#pragma unroll
    for (int mi = 0; mi < 2; ++mi)
#pragma unroll
        for (int ni = 0; ni < 8; ++ni)
#pragma unroll
            for (int j = 0; j < 4; ++j) acc[mi][ni][j] = 0;

#pragma unroll
    for (int s = 0; s < STAGES - 1; ++s) {
        load_stage(sb + s * STAGE_BYTES, m0, n0, s, tid);
        cp_commit();
    }

    const int mat = lane >> 3;
    const int rsel = (lane & 7) + (mat & 1) * 8;
    const int csel = mat >> 1;

    for (int kt = 0; kt < KTILES; ++kt) {
        cp_wait<STAGES - 2>();
        __syncthreads();

        int nxt = kt + STAGES - 1;
        if (nxt < KTILES)
            load_stage(sb + (nxt % STAGES) * STAGE_BYTES, m0, n0, nxt, tid);
        cp_commit();

        const uint32_t aT = sb + (kt % STAGES) * STAGE_BYTES;
        const uint32_t bT = aT + BM * BK;

#pragma unroll
        for (int ksi = 0; ksi < 4; ++ksi) {
            const int ks = (ksi + phase) & 3;     // runtime, address-only
            const int ch = ks * 2 + csel;
            uint32_t aF[2][4];
#pragma unroll
            for (int mi = 0; mi < 2; ++mi) {
                int row = wm * 32 + mi * 16 + rsel;
                ldmatrix_x4(aF[mi], aT + row * BK + (((uint32_t)(ch ^ (row & 7))) << 4));
            }
            uint32_t bF[8][2];
#pragma unroll
            for (int nj = 0; nj < 4; ++nj) {      // natural order, const indices
                int n = wn * 64 + nj * 16 + rsel;
                uint32_t r[4];
                ldmatrix_x4(r, bT + n * BK + (((uint32_t)(ch ^ (n & 7))) << 4));
                bF[nj * 2][0] = r[0]; bF[nj * 2 + 1][0] = r[1];
                bF[nj * 2][1] = r[2]; bF[nj * 2 + 1][1] = r[3];
            }
#pragma unroll
            for (int mi = 0; mi < 2; ++mi)
#pragma unroll
                for (int ni = 0; ni < 8; ++ni)
                    mma_s8(acc[mi][ni], aF[mi], bF[ni]);
        }
    }
    cp_wait<0>();

    // ---- epilogue: scale + bias, direct-to-global (no staging, no syncs) ----
    const float as = *act_scale_p;
    const int r4 = lane >> 2;             // 0..7
    const int c2 = (lane & 3) * 2;        // 0,2,4,6

#pragma unroll
    for (int ni = 0; ni < 8; ++ni) {
        int gc = n0 + wn * 64 + ni * 8 + c2;
        float sw0 = as * wscale[gc],     bv0 = bias[gc];
        float sw1 = as * wscale[gc + 1], bv1 = bias[gc + 1];
#pragma unroll
        for (int mi = 0; mi < 2; ++mi) {
            int r = m0 + wm * 32 + mi * 16 + r4;
            float2 v0, v1;
            v0.x = fmaf(__int2float_rn(acc[mi][ni][0]), sw0, bv0);
            v0.y = fmaf(__int2float_rn(acc[mi][ni][1]), sw1, bv1);
            v1.x = fmaf(__int2float_rn(acc[mi][ni][2]), sw0, bv0);
            v1.y = fmaf(__int2float_rn(acc[mi][ni][3]), sw1, bv1);
            *reinterpret_cast<float2*>(&out[(size_t)r * ODIM + gc])       = v0;
            *reinterpret_cast<float2*>(&out[(size_t)(r + 8) * ODIM + gc]) = v1;
        }
    }
}

// ---------------------------------------------------------------------------
extern "C" void kernel_launch(void* const* d_in, const int* in_sizes, int n_in,
                              void* d_out, int out_size) {
    (void)in_sizes; (void)n_in; (void)out_size;
    const float* x         = (const float*)d_in[0];
    const float* weight    = (const float*)d_in[1];
    const float* bias      = (const float*)d_in[2];
    const float* act_scale = (const float*)d_in[3];
    const int*   act_zp    = (const int*)d_in[4];
    const float* wscale    = (const float*)d_in[5];
    const int*   wzp       = (const int*)d_in[6];
    float* out = (float*)d_out;

    cudaFuncSetAttribute(gemm_q_kernel, cudaFuncAttributeMaxDynamicSharedMemorySize, GEMM_SMEM);

    quant_fused_kernel<<<2 * QB, 256>>>(x, act_scale, act_zp, weight, wscale, wzp);

    dim3 grid(ODIM / BN, NROWS / BM);   // (32, 32)
    gemm_q_kernel<<<grid, 256, GEMM_SMEM>>>(bias, act_scale, wscale, out);
}